// round 12
// baseline (speedup 1.0000x reference)
#include <cuda_runtime.h>
#include <math.h>

// ---------------- problem constants ----------------
#define T_   1024            // tokens (B*S)
#define H_   2048            // hidden
#define NH_  16
#define HD_  128
#define E_   60
#define K_   4
#define I_   1408
#define SI_  5632
#define QKVD 6144            // 3*NH*HD
#define NPAIR (T_*K_)        // 4096

typedef unsigned long long ull_t;

// packed f32x2 helpers (sm_103a dual-rate fp32 FMA)
__device__ __forceinline__ ull_t dup2(float x) {
    ull_t r; unsigned u = __float_as_uint(x);
    asm("mov.b64 %0, {%1, %1};" : "=l"(r) : "r"(u));
    return r;
}
__device__ __forceinline__ void fma2(ull_t& acc, ull_t a, ull_t b) {
    asm("fma.rn.f32x2 %0, %1, %2, %0;" : "+l"(acc) : "l"(a), "l"(b));
}
__device__ __forceinline__ float2 unpack2(ull_t v) {
    float2 f;
    asm("mov.b64 {%0, %1}, %2;" : "=f"(f.x), "=f"(f.y) : "l"(v));
    return f;
}

// XOR swizzle for transposed [k][m] shared tiles (k-tile depth 16):
// element (k,m) stored at column m ^ (((k>>2)&3)*8). Conflict-free scalar
// stores and conflict-free 16B/8B loads (kk is an unroll constant).
#define KSWZ(k)  ((((k) >> 2) & 3) * 8)

// ---------------- scratch (device globals; no allocs allowed) ----------------
__device__ float g_h1 [T_*H_];
__device__ float g_qkv[(size_t)T_*QKVD];
__device__ float g_scores[(size_t)NH_*T_*T_];
__device__ float g_attn[T_*H_];
__device__ float g_x1 [T_*H_];
__device__ float g_h2 [T_*H_];
__device__ float g_tw [NPAIR];
__device__ int   g_ti [NPAIR];
__device__ int   g_cnt[64];
__device__ int   g_off[64];
__device__ int   g_cur[64];
__device__ int   g_tok[NPAIR];
__device__ float g_pw [NPAIR];
__device__ int   g_ppos[NPAIR];
__device__ float g_act [(size_t)NPAIR*I_];
__device__ float g_dexp[(size_t)NPAIR*H_];
__device__ float g_sact[(size_t)T_*SI_];
__device__ float g_so  [T_*H_];
__device__ float g_sgl [T_];

// ---------------- rmsnorm ----------------
__global__ void rmsnorm_kernel(const float* __restrict__ x, const float* __restrict__ w,
                               float* __restrict__ out)
{
    int t = blockIdx.x;
    const float* xr = x + (size_t)t * H_;
    float* orow = out + (size_t)t * H_;
    __shared__ float red[256];
    int tid = threadIdx.x;
    float s = 0.f;
    for (int i = tid; i < H_; i += 256) { float v = xr[i]; s += v * v; }
    red[tid] = s; __syncthreads();
    for (int o = 128; o > 0; o >>= 1) { if (tid < o) red[tid] += red[tid + o]; __syncthreads(); }
    float inv = rsqrtf(red[0] / (float)H_ + 1e-6f);
    for (int i = tid; i < H_; i += 256) orow[i] = xr[i] * inv * w[i];
}

// ======== big dense GEMM: C[M,N]=A[M,K]*B[N,K]^T (+bias)(+res) ========
// 128x128 tile, 8x8 per thread, swizzled smem, f32x2 accumulators.
__global__ __launch_bounds__(256) void gemm_nt128_kernel(
    const float* __restrict__ A, const float* __restrict__ B,
    const float* __restrict__ bias, const float* __restrict__ res,
    float* __restrict__ C, int M, int N, int K)
{
    __shared__ float As[16][128];
    __shared__ float Bs[16][128];
    int tid = threadIdx.x;
    int tx = tid & 15, ty = tid >> 4;       // compute: rows ty*8.., cols tx*8..
    int lr = tid >> 1, lc = (tid & 1) * 8;  // load: row lr, k-cols lc..lc+7
    int n0 = blockIdx.x * 128, m0 = blockIdx.y * 128;
    const float* Ap = A + (size_t)(m0 + lr) * K + lc;
    const float* Bp = B + (size_t)(n0 + lr) * K + lc;
    ull_t acc[8][4] = {};
    for (int k0 = 0; k0 < K; k0 += 16) {
        float4 a0 = *(const float4*)(Ap + k0);
        float4 a1 = *(const float4*)(Ap + k0 + 4);
        float4 b0 = *(const float4*)(Bp + k0);
        float4 b1 = *(const float4*)(Bp + k0 + 4);
        float av[8] = {a0.x,a0.y,a0.z,a0.w,a1.x,a1.y,a1.z,a1.w};
        float bv[8] = {b0.x,b0.y,b0.z,b0.w,b1.x,b1.y,b1.z,b1.w};
        __syncthreads();
#pragma unroll
        for (int i = 0; i < 8; ++i) {
            int k = lc + i;
            int c = lr ^ KSWZ(k);
            As[k][c] = av[i];
            Bs[k][c] = bv[i];
        }
        __syncthreads();
#pragma unroll
        for (int kk = 0; kk < 16; ++kk) {
            int s = KSWZ(kk);
            int acol = (ty*8) ^ s;
            int bcol = (tx*8) ^ s;
            float4 av0 = *(const float4*)&As[kk][acol];
            float4 av1 = *(const float4*)&As[kk][acol + 4];
            ull_t b[4];
#pragma unroll
            for (int j = 0; j < 4; ++j) b[j] = *(const ull_t*)&Bs[kk][bcol + 2*j];
            ull_t a[8] = {dup2(av0.x), dup2(av0.y), dup2(av0.z), dup2(av0.w),
                          dup2(av1.x), dup2(av1.y), dup2(av1.z), dup2(av1.w)};
#pragma unroll
            for (int i = 0; i < 8; ++i)
#pragma unroll
                for (int j = 0; j < 4; ++j)
                    fma2(acc[i][j], a[i], b[j]);
        }
    }
#pragma unroll
    for (int i = 0; i < 8; ++i) {
        int m = m0 + ty*8 + i;
#pragma unroll
        for (int j = 0; j < 4; ++j) {
            float2 p = unpack2(acc[i][j]);
            int n = n0 + tx*8 + 2*j;
            if (bias) { p.x += bias[n]; p.y += bias[n+1]; }
            if (res)  { p.x += res[(size_t)m*N + n]; p.y += res[(size_t)m*N + n + 1]; }
            *(float2*)&C[(size_t)m*N + n] = p;
        }
    }
}

// ---------------- RoPE (NeoX, full head dim, in place on q and k) ----------------
__global__ void rope_kernel(float* __restrict__ qkv, const int* __restrict__ pos)
{
    int t = blockIdx.x, head = blockIdx.y, d = threadIdx.x; // d in [0,64)
    float p = (float)pos[t];
    float inv = powf(1000000.f, -((float)(2 * d)) / 128.f);
    float ang = p * inv;
    float c = cosf(ang), s = sinf(ang);
    float* q = qkv + (size_t)t * QKVD + head * HD_;
    float* k = q + NH_ * HD_;
    float q1 = q[d], q2 = q[d + 64];
    q[d] = q1 * c - q2 * s;  q[d + 64] = q2 * c + q1 * s;
    float k1 = k[d], k2 = k[d + 64];
    k[d] = k1 * c - k2 * s;  k[d + 64] = k2 * c + k1 * s;
}

// ---------------- QK^T with causal mask + scale ----------------
__global__ __launch_bounds__(256) void qk_kernel(const float* __restrict__ qkv,
                                                 float* __restrict__ scores)
{
    int head = blockIdx.z;
    int n0 = blockIdx.x * 64, m0 = blockIdx.y * 64;
    if (n0 > m0) return;  // tile entirely above causal diagonal
    __shared__ float As[16][64];
    __shared__ float Bs[16][64];
    int tid = threadIdx.x;
    int tx = tid & 15, ty = tid >> 4;
    int lr = tid >> 2, lc = (tid & 3) * 4;
    int swc = lr ^ KSWZ(lc);
    const float* Ap = qkv + (size_t)(m0 + lr) * QKVD + head * HD_ + lc;
    const float* Bp = qkv + (size_t)(n0 + lr) * QKVD + NH_*HD_ + head * HD_ + lc;
    ull_t acc2[4][2] = {};
    for (int k0 = 0; k0 < HD_; k0 += 16) {
        float4 a4 = *(const float4*)(Ap + k0);
        float4 b4 = *(const float4*)(Bp + k0);
        __syncthreads();
        As[lc+0][swc] = a4.x; As[lc+1][swc] = a4.y; As[lc+2][swc] = a4.z; As[lc+3][swc] = a4.w;
        Bs[lc+0][swc] = b4.x; Bs[lc+1][swc] = b4.y; Bs[lc+2][swc] = b4.z; Bs[lc+3][swc] = b4.w;
        __syncthreads();
#pragma unroll
        for (int kk = 0; kk < 16; ++kk) {
            int s = KSWZ(kk);
            float4 av = *(const float4*)&As[kk][(ty*4) ^ s];
            ull_t b0 = *(const ull_t*)&Bs[kk][(tx*4) ^ s];
            ull_t b1 = *(const ull_t*)&Bs[kk][((tx*4) ^ s) + 2];
            ull_t a0 = dup2(av.x), a1 = dup2(av.y), a2 = dup2(av.z), a3 = dup2(av.w);
            fma2(acc2[0][0], a0, b0); fma2(acc2[0][1], a0, b1);
            fma2(acc2[1][0], a1, b0); fma2(acc2[1][1], a1, b1);
            fma2(acc2[2][0], a2, b0); fma2(acc2[2][1], a2, b1);
            fma2(acc2[3][0], a3, b0); fma2(acc2[3][1], a3, b1);
        }
    }
    const float scale = 0.08838834764831845f;
    float* sh = scores + (size_t)head * T_ * T_;
#pragma unroll
    for (int i = 0; i < 4; ++i) {
        int m = m0 + ty*4 + i;
#pragma unroll
        for (int j2 = 0; j2 < 2; ++j2) {
            float2 p = unpack2(acc2[i][j2]);
            int n = n0 + tx*4 + j2*2;
            sh[(size_t)m * T_ + n]     = (n     <= m) ? p.x * scale : -1e30f;
            sh[(size_t)m * T_ + n + 1] = (n + 1 <= m) ? p.y * scale : -1e30f;
        }
    }
}

// ---------------- row softmax (causal length i+1), zero-fill tail ----------------
__global__ void softmax_kernel(float* __restrict__ scores)
{
    int i = blockIdx.x, head = blockIdx.y;
    float* row = scores + (size_t)head * T_ * T_ + (size_t)i * T_;
    int L = i + 1;
    __shared__ float red[256];
    int tid = threadIdx.x;
    float mx = -1e30f;
    for (int j = tid; j < L; j += 256) mx = fmaxf(mx, row[j]);
    red[tid] = mx; __syncthreads();
    for (int o = 128; o > 0; o >>= 1) { if (tid < o) red[tid] = fmaxf(red[tid], red[tid+o]); __syncthreads(); }
    mx = red[0]; __syncthreads();
    float s = 0.f;
    for (int j = tid; j < L; j += 256) s += expf(row[j] - mx);
    red[tid] = s; __syncthreads();
    for (int o = 128; o > 0; o >>= 1) { if (tid < o) red[tid] += red[tid+o]; __syncthreads(); }
    float inv = 1.f / red[0];
    for (int j = tid; j < T_; j += 256)
        row[j] = (j < L) ? expf(row[j] - mx) * inv : 0.f;
}

// ---------------- P @ V  (NN, BN=128=HD), causal-truncated k loop ----------------
#define VSTRIDE 132
__global__ __launch_bounds__(256) void pv_kernel(const float* __restrict__ scores,
                                                 const float* __restrict__ qkv,
                                                 float* __restrict__ attn)
{
    int head = blockIdx.y;
    int m0 = blockIdx.x * 64;
    __shared__ float Ps[16][64];
    __shared__ float Vs[16][VSTRIDE];
    int tid = threadIdx.x;
    int tx = tid & 15, ty = tid >> 4;
    int lr = tid >> 2, lc = (tid & 3) * 4;
    int swc = lr ^ KSWZ(lc);
    int vr = tid >> 4, vc = (tid & 15) * 8;
    const float* P = scores + (size_t)head * T_ * T_;
    const float* Vb = qkv + 2 * NH_ * HD_ + head * HD_;
    ull_t acc2[4][4] = {};
    for (int j0 = 0; j0 < m0 + 64; j0 += 16) {
        float4 p4 = *(const float4*)(P + (size_t)(m0 + lr) * T_ + j0 + lc);
        float4 va = *(const float4*)(Vb + (size_t)(j0 + vr) * QKVD + vc);
        float4 vb = *(const float4*)(Vb + (size_t)(j0 + vr) * QKVD + vc + 4);
        __syncthreads();
        Ps[lc+0][swc] = p4.x; Ps[lc+1][swc] = p4.y; Ps[lc+2][swc] = p4.z; Ps[lc+3][swc] = p4.w;
        *(float4*)&Vs[vr][vc]     = va;
        *(float4*)&Vs[vr][vc + 4] = vb;
        __syncthreads();
#pragma unroll
        for (int kk = 0; kk < 16; ++kk) {
            int s = KSWZ(kk);
            float4 av = *(const float4*)&Ps[kk][(ty*4) ^ s];
            ull_t b0 = *(const ull_t*)&Vs[kk][tx*8];
            ull_t b1 = *(const ull_t*)&Vs[kk][tx*8 + 2];
            ull_t b2 = *(const ull_t*)&Vs[kk][tx*8 + 4];
            ull_t b3 = *(const ull_t*)&Vs[kk][tx*8 + 6];
            ull_t a0 = dup2(av.x), a1 = dup2(av.y), a2 = dup2(av.z), a3 = dup2(av.w);
            fma2(acc2[0][0], a0, b0); fma2(acc2[0][1], a0, b1); fma2(acc2[0][2], a0, b2); fma2(acc2[0][3], a0, b3);
            fma2(acc2[1][0], a1, b0); fma2(acc2[1][1], a1, b1); fma2(acc2[1][2], a1, b2); fma2(acc2[1][3], a1, b3);
            fma2(acc2[2][0], a2, b0); fma2(acc2[2][1], a2, b1); fma2(acc2[2][2], a2, b2); fma2(acc2[2][3], a2, b3);
            fma2(acc2[3][0], a3, b0); fma2(acc2[3][1], a3, b1); fma2(acc2[3][2], a3, b2); fma2(acc2[3][3], a3, b3);
        }
    }
#pragma unroll
    for (int i = 0; i < 4; ++i) {
        int m = m0 + ty*4 + i;
#pragma unroll
        for (int j2 = 0; j2 < 4; ++j2) {
            float2 p = unpack2(acc2[i][j2]);
            attn[(size_t)m * H_ + head * HD_ + tx*8 + j2*2]     = p.x;
            attn[(size_t)m * H_ + head * HD_ + tx*8 + j2*2 + 1] = p.y;
        }
    }
}

// ---------------- router ----------------
__global__ void router_kernel(const float* __restrict__ h2, const float* __restrict__ gate_w,
                              const float* __restrict__ sg_w,
                              float* __restrict__ tw, int* __restrict__ ti,
                              float* __restrict__ sgl)
{
    int t = blockIdx.x;
    __shared__ float hs[H_];
    __shared__ float logits[E_];
    __shared__ float sgp[8];
    int tid = threadIdx.x;
    for (int i = tid; i < H_; i += 256) hs[i] = h2[(size_t)t * H_ + i];
    __syncthreads();
    int warp = tid >> 5, lane = tid & 31;
    for (int e = warp; e < E_; e += 8) {
        float s = 0.f;
        const float* w = gate_w + (size_t)e * H_;
        for (int i = lane; i < H_; i += 32) s += hs[i] * w[i];
        for (int o = 16; o > 0; o >>= 1) s += __shfl_xor_sync(~0u, s, o);
        if (lane == 0) logits[e] = s;
    }
    {
        float s = 0.f;
        for (int i = tid; i < H_; i += 256) s += hs[i] * sg_w[i];
        for (int o = 16; o > 0; o >>= 1) s += __shfl_xor_sync(~0u, s, o);
        if (lane == 0) sgp[warp] = s;
    }
    __syncthreads();
    if (tid == 0) {
        float sd = 0.f;
        for (int w = 0; w < 8; ++w) sd += sgp[w];
        sgl[t] = 1.f / (1.f + expf(-sd));
        float mx = -1e30f;
        for (int e = 0; e < E_; ++e) mx = fmaxf(mx, logits[e]);
        float p[E_]; float sum = 0.f;
        for (int e = 0; e < E_; ++e) { p[e] = expf(logits[e] - mx); sum += p[e]; }
        float inv = 1.f / sum;
        int idx[K_]; float val[K_]; float tot = 0.f;
        for (int k = 0; k < K_; ++k) {
            float best = -1.f; int bi = 0;
            for (int e = 0; e < E_; ++e) if (p[e] > best) { best = p[e]; bi = e; }
            idx[k] = bi; val[k] = best * inv; tot += val[k]; p[bi] = -2.f;
        }
        for (int k = 0; k < K_; ++k) { ti[t*K_ + k] = idx[k]; tw[t*K_ + k] = val[k] / tot; }
    }
}

// ---------------- expert routing bookkeeping ----------------
__global__ void zero_counts_kernel(int* cnt) { if (threadIdx.x < 64) cnt[threadIdx.x] = 0; }

__global__ void count_kernel(const int* __restrict__ ti, int* cnt)
{
    int i = blockIdx.x * 256 + threadIdx.x;
    if (i < NPAIR) atomicAdd(&cnt[ti[i]], 1);
}

__global__ void scan_kernel(const int* __restrict__ cnt, int* off, int* cur)
{
    if (threadIdx.x == 0) {
        int s = 0;
        for (int e = 0; e < E_; ++e) { off[e] = s; cur[e] = s; s += cnt[e]; }
        off[E_] = s;
    }
}

__global__ void scatter_kernel(const int* __restrict__ ti, const float* __restrict__ tw,
                               int* cur, int* __restrict__ tok, float* __restrict__ pw,
                               int* __restrict__ ppos)
{
    int i = blockIdx.x * 256 + threadIdx.x;
    if (i < NPAIR) {
        int e = ti[i];
        int pos = atomicAdd(&cur[e], 1);
        tok[pos] = i >> 2;
        pw[pos] = tw[i];
        ppos[i] = pos;
    }
}

// ======== fused gate/up + silu, tile 64(M) x 128(N), 4x8 per thread ========
__device__ __forceinline__ void gateup128_body(
    const float* __restrict__ Arows, const float* __restrict__ Wg,
    const float* __restrict__ Wu, float* __restrict__ outp, int outStride,
    int n0, int m0, int M, const int* __restrict__ tok, int base)
{
    __shared__ float As[16][64];
    __shared__ float Gs[16][128];
    __shared__ float Us[16][128];
    int tid = threadIdx.x;
    int tx = tid & 15, ty = tid >> 4;        // compute: rows ty*4.., cols tx*8..
    int ar = tid >> 2, ac = (tid & 3) * 4;   // A load: row ar, k-cols ac..ac+3
    int gr = tid >> 1, gc = (tid & 1) * 8;   // G/U load: row gr, k-cols gc..gc+7
    int aswc = ar ^ KSWZ(ac);
    int arow = m0 + ar;
    const float* Ap;
    if (tok) {
        int tk = tok[base + ((arow < M) ? arow : 0)];
        Ap = Arows + (size_t)tk * H_ + ac;
    } else {
        Ap = Arows + (size_t)arow * H_ + ac;
    }
    const float* Gp = Wg + (size_t)(n0 + gr) * H_ + gc;
    const float* Up = Wu + (size_t)(n0 + gr) * H_ + gc;
    ull_t ag[4][4] = {}, au[4][4] = {};
    for (int k0 = 0; k0 < H_; k0 += 16) {
        float4 a4 = *(const float4*)(Ap + k0);
        float4 g0 = *(const float4*)(Gp + k0);
        float4 g1 = *(const float4*)(Gp + k0 + 4);
        float4 u0 = *(const float4*)(Up + k0);
        float4 u1 = *(const float4*)(Up + k0 + 4);
        float gv[8] = {g0.x,g0.y,g0.z,g0.w,g1.x,g1.y,g1.z,g1.w};
        float uv[8] = {u0.x,u0.y,u0.z,u0.w,u1.x,u1.y,u1.z,u1.w};
        __syncthreads();
        As[ac+0][aswc] = a4.x; As[ac+1][aswc] = a4.y; As[ac+2][aswc] = a4.z; As[ac+3][aswc] = a4.w;
#pragma unroll
        for (int i = 0; i < 8; ++i) {
            int k = gc + i;
            int c = gr ^ KSWZ(k);
            Gs[k][c] = gv[i];
            Us[k][c] = uv[i];
        }
        __syncthreads();
#pragma unroll
        for (int kk = 0; kk < 16; ++kk) {
            int s = KSWZ(kk);
            float4 av = *(const float4*)&As[kk][(ty*4) ^ s];
            int bcol = (tx*8) ^ s;
            ull_t gb[4], ub[4];
#pragma unroll
            for (int j = 0; j < 4; ++j) {
                gb[j] = *(const ull_t*)&Gs[kk][bcol + 2*j];
                ub[j] = *(const ull_t*)&Us[kk][bcol + 2*j];
            }
            ull_t a[4] = {dup2(av.x), dup2(av.y), dup2(av.z), dup2(av.w)};
#pragma unroll
            for (int i = 0; i < 4; ++i)
#pragma unroll
                for (int j = 0; j < 4; ++j) {
                    fma2(ag[i][j], a[i], gb[j]);
                    fma2(au[i][j], a[i], ub[j]);
                }
        }
    }
#pragma unroll
    for (int i = 0; i < 4; ++i) {
        int row = m0 + ty*4 + i;
        if (row < M) {
#pragma unroll
            for (int j = 0; j < 4; ++j) {
                float2 g = unpack2(ag[i][j]);
                float2 u = unpack2(au[i][j]);
                float2 o;
                o.x = (g.x / (1.f + expf(-g.x))) * u.x;
                o.y = (g.y / (1.f + expf(-g.y))) * u.y;
                *(float2*)&outp[(size_t)row * outStride + n0 + tx*8 + 2*j] = o;
            }
        }
    }
}

__global__ __launch_bounds__(256) void expert_gateup_kernel(
    const float* __restrict__ h2, const float* __restrict__ Wg_all,
    const float* __restrict__ Wu_all, const int* __restrict__ cnt,
    const int* __restrict__ off, const int* __restrict__ tok,
    float* __restrict__ act)
{
    int e = blockIdx.y;
    int n0 = blockIdx.x * 128;
    int M = cnt[e], base = off[e];
    const float* Wg = Wg_all + (size_t)e * I_ * H_;
    const float* Wu = Wu_all + (size_t)e * I_ * H_;
    float* outp = act + (size_t)base * I_;
    for (int m0 = 0; m0 < M; m0 += 64)
        gateup128_body(h2, Wg, Wu, outp, I_, n0, m0, M, tok, base);
}

__global__ __launch_bounds__(256) void shared_gateup_kernel(
    const float* __restrict__ h2, const float* __restrict__ Wg,
    const float* __restrict__ Wu, float* __restrict__ sact)
{
    int n0 = blockIdx.x * 128;
    int m0 = blockIdx.y * 64;
    gateup128_body(h2, Wg, Wu, sact, SI_, n0, m0, T_, nullptr, 0);
}

// ======== expert down: tile 64(M) x 128(N), 4x8 per thread, K=I ========
__global__ __launch_bounds__(256) void expert_down_kernel(
    const float* __restrict__ act, const float* __restrict__ Wd_all,
    const int* __restrict__ cnt, const int* __restrict__ off,
    const float* __restrict__ pw, float* __restrict__ dexp)
{
    int e = blockIdx.y;
    int n0 = blockIdx.x * 128;
    int M = cnt[e], base = off[e];
    const float* Wd = Wd_all + (size_t)e * H_ * I_;
    const float* A = act + (size_t)base * I_;
    __shared__ float As[16][64];
    __shared__ float Bs[16][128];
    int tid = threadIdx.x;
    int tx = tid & 15, ty = tid >> 4;
    int ar = tid >> 2, ac = (tid & 3) * 4;
    int gr = tid >> 1, gc = (tid & 1) * 8;
    int aswc = ar ^ KSWZ(ac);
    const float* Bp = Wd + (size_t)(n0 + gr) * I_ + gc;
    for (int m0 = 0; m0 < M; m0 += 64) {
        int arow = m0 + ar;
        const float* Ap = A + (size_t)((arow < M) ? arow : 0) * I_ + ac;
        ull_t acc[4][4] = {};
        for (int k0 = 0; k0 < I_; k0 += 16) {
            float4 a4 = *(const float4*)(Ap + k0);
            float4 b0 = *(const float4*)(Bp + k0);
            float4 b1 = *(const float4*)(Bp + k0 + 4);
            float bv[8] = {b0.x,b0.y,b0.z,b0.w,b1.x,b1.y,b1.z,b1.w};
            __syncthreads();
            As[ac+0][aswc] = a4.x; As[ac+1][aswc] = a4.y; As[ac+2][aswc] = a4.z; As[ac+3][aswc] = a4.w;
#pragma unroll
            for (int i = 0; i < 8; ++i) {
                int k = gc + i;
                Bs[k][gr ^ KSWZ(k)] = bv[i];
            }
            __syncthreads();
#pragma unroll
            for (int kk = 0; kk < 16; ++kk) {
                int s = KSWZ(kk);
                float4 av = *(const float4*)&As[kk][(ty*4) ^ s];
                int bcol = (tx*8) ^ s;
                ull_t b[4];
#pragma unroll
                for (int j = 0; j < 4; ++j) b[j] = *(const ull_t*)&Bs[kk][bcol + 2*j];
                ull_t a[4] = {dup2(av.x), dup2(av.y), dup2(av.z), dup2(av.w)};
#pragma unroll
                for (int i = 0; i < 4; ++i)
#pragma unroll
                    for (int j = 0; j < 4; ++j)
                        fma2(acc[i][j], a[i], b[j]);
            }
        }
#pragma unroll
        for (int i = 0; i < 4; ++i) {
            int row = m0 + ty*4 + i;
            if (row < M) {
                float w = pw[base + row];
#pragma unroll
                for (int j = 0; j < 4; ++j) {
                    float2 p = unpack2(acc[i][j]);
                    p.x *= w; p.y *= w;
                    *(float2*)&dexp[(size_t)(base + row) * H_ + n0 + tx*8 + 2*j] = p;
                }
            }
        }
    }
}

// ---------------- final combine: residual + gated shared + 4 routed pairs ------
__global__ void combine_kernel(const float* __restrict__ x1, const float* __restrict__ so,
                               const float* __restrict__ sgl, const float* __restrict__ dexp,
                               const int* __restrict__ ppos, float* __restrict__ out)
{
    int t = blockIdx.x;
    float g = sgl[t];
    int p0 = ppos[t*K_ + 0], p1 = ppos[t*K_ + 1], p2 = ppos[t*K_ + 2], p3 = ppos[t*K_ + 3];
    for (int h = threadIdx.x; h < H_; h += 256) {
        float v = x1[(size_t)t*H_ + h] + g * so[(size_t)t*H_ + h];
        v += dexp[(size_t)p0*H_ + h];
        v += dexp[(size_t)p1*H_ + h];
        v += dexp[(size_t)p2*H_ + h];
        v += dexp[(size_t)p3*H_ + h];
        out[(size_t)t*H_ + h] = v;
    }
}

// ---------------- launch ----------------
template <typename Tp>
static Tp* sym_addr(const void* symbol)
{
    void* p = nullptr;
    cudaGetSymbolAddress(&p, symbol);
    return (Tp*)p;
}

extern "C" void kernel_launch(void* const* d_in, const int* in_sizes, int n_in,
                              void* d_out, int out_size)
{
    const int*   positions = (const int*)  d_in[0];
    const float* x         = (const float*)d_in[1];
    const float* ln1_w     = (const float*)d_in[2];
    const float* ln2_w     = (const float*)d_in[3];
    const float* Wqkv      = (const float*)d_in[4];
    const float* bqkv      = (const float*)d_in[5];
    const float* Wo        = (const float*)d_in[6];
    const float* gate_w    = (const float*)d_in[7];
    const float* W_gate    = (const float*)d_in[8];
    const float* W_up      = (const float*)d_in[9];
    const float* W_down    = (const float*)d_in[10];
    const float* Ws_gate   = (const float*)d_in[11];
    const float* Ws_up     = (const float*)d_in[12];
    const float* Ws_down   = (const float*)d_in[13];
    const float* sg_w      = (const float*)d_in[14];
    float* out = (float*)d_out;

    float* h1   = sym_addr<float>(g_h1);
    float* qkv  = sym_addr<float>(g_qkv);
    float* sc   = sym_addr<float>(g_scores);
    float* attn = sym_addr<float>(g_attn);
    float* x1   = sym_addr<float>(g_x1);
    float* h2   = sym_addr<float>(g_h2);
    float* tw   = sym_addr<float>(g_tw);
    int*   ti   = sym_addr<int>(g_ti);
    int*   cnt  = sym_addr<int>(g_cnt);
    int*   off  = sym_addr<int>(g_off);
    int*   cur  = sym_addr<int>(g_cur);
    int*   tok  = sym_addr<int>(g_tok);
    float* pw   = sym_addr<float>(g_pw);
    int*   ppos = sym_addr<int>(g_ppos);
    float* act  = sym_addr<float>(g_act);
    float* dexp = sym_addr<float>(g_dexp);
    float* sact = sym_addr<float>(g_sact);
    float* so   = sym_addr<float>(g_so);
    float* sgl  = sym_addr<float>(g_sgl);

    // ---- attention ----
    rmsnorm_kernel<<<T_, 256>>>(x, ln1_w, h1);
    gemm_nt128_kernel<<<dim3(QKVD/128, T_/128), 256>>>(h1, Wqkv, bqkv, nullptr, qkv, T_, QKVD, H_);
    rope_kernel<<<dim3(T_, NH_), 64>>>(qkv, positions);
    qk_kernel<<<dim3(T_/64, T_/64, NH_), 256>>>(qkv, sc);
    softmax_kernel<<<dim3(T_, NH_), 256>>>(sc);
    pv_kernel<<<dim3(T_/64, NH_), 256>>>(sc, qkv, attn);
    gemm_nt128_kernel<<<dim3(H_/128, T_/128), 256>>>(attn, Wo, nullptr, x, x1, T_, H_, H_);

    // ---- MoE ----
    rmsnorm_kernel<<<T_, 256>>>(x1, ln2_w, h2);
    router_kernel<<<T_, 256>>>(h2, gate_w, sg_w, tw, ti, sgl);
    zero_counts_kernel<<<1, 64>>>(cnt);
    count_kernel<<<NPAIR/256, 256>>>(ti, cnt);
    scan_kernel<<<1, 32>>>(cnt, off, cur);
    scatter_kernel<<<NPAIR/256, 256>>>(ti, tw, cur, tok, pw, ppos);
    expert_gateup_kernel<<<dim3(I_/128, E_), 256>>>(h2, W_gate, W_up, cnt, off, tok, act);
    expert_down_kernel<<<dim3(H_/128, E_), 256>>>(act, W_down, cnt, off, pw, dexp);
    shared_gateup_kernel<<<dim3(SI_/128, T_/64), 256>>>(h2, Ws_gate, Ws_up, sact);
    gemm_nt128_kernel<<<dim3(H_/128, T_/128), 256>>>(sact, Ws_down, nullptr, nullptr, so, T_, H_, SI_);
    combine_kernel<<<T_, 256>>>(x1, so, sgl, dexp, ppos, out);
}

// round 13
// speedup vs baseline: 1.4260x; 1.4260x over previous
#include <cuda_runtime.h>
#include <math.h>

// ---------------- problem constants ----------------
#define T_   1024            // tokens (B*S)
#define H_   2048            // hidden
#define NH_  16
#define HD_  128
#define E_   60
#define K_   4
#define I_   1408
#define SI_  5632
#define QKVD 6144            // 3*NH*HD
#define NPAIR (T_*K_)        // 4096

typedef unsigned long long ull_t;

// packed f32x2 helpers (sm_103a dual-rate fp32 FMA)
__device__ __forceinline__ ull_t dup2(float x) {
    ull_t r; unsigned u = __float_as_uint(x);
    asm("mov.b64 %0, {%1, %1};" : "=l"(r) : "r"(u));
    return r;
}
__device__ __forceinline__ void fma2(ull_t& acc, ull_t a, ull_t b) {
    asm("fma.rn.f32x2 %0, %1, %2, %0;" : "+l"(acc) : "l"(a), "l"(b));
}
__device__ __forceinline__ float2 unpack2(ull_t v) {
    float2 f;
    asm("mov.b64 {%0, %1}, %2;" : "=f"(f.x), "=f"(f.y) : "l"(v));
    return f;
}

// XOR swizzle for transposed [k][m] 64-wide shared tiles (k-depth 16):
// element (k,m) stored at column m ^ (((k>>2)&3)*8). Conflict-free scalar
// stores and conflict-free 16B/8B loads (kk is an unroll constant).
#define KSWZ(k)  ((((k) >> 2) & 3) * 8)

// ---------------- scratch (device globals; no allocs allowed) ----------------
__device__ float g_h1 [T_*H_];
__device__ float g_qkv[(size_t)T_*QKVD];
__device__ float g_scores[(size_t)NH_*T_*T_];
__device__ float g_attn[T_*H_];
__device__ float g_x1 [T_*H_];
__device__ float g_h2 [T_*H_];
__device__ float g_tw [NPAIR];
__device__ int   g_ti [NPAIR];
__device__ int   g_cnt[64];
__device__ int   g_off[64];
__device__ int   g_cur[64];
__device__ int   g_tok[NPAIR];
__device__ float g_pw [NPAIR];
__device__ int   g_ppos[NPAIR];
__device__ float g_act [(size_t)NPAIR*I_];
__device__ float g_dexp[(size_t)NPAIR*H_];
__device__ float g_sact[(size_t)T_*SI_];
__device__ float g_so  [T_*H_];
__device__ float g_sgl [T_];

// ---------------- rmsnorm ----------------
__global__ void rmsnorm_kernel(const float* __restrict__ x, const float* __restrict__ w,
                               float* __restrict__ out)
{
    int t = blockIdx.x;
    const float* xr = x + (size_t)t * H_;
    float* orow = out + (size_t)t * H_;
    __shared__ float red[256];
    int tid = threadIdx.x;
    float s = 0.f;
    for (int i = tid; i < H_; i += 256) { float v = xr[i]; s += v * v; }
    red[tid] = s; __syncthreads();
    for (int o = 128; o > 0; o >>= 1) { if (tid < o) red[tid] += red[tid + o]; __syncthreads(); }
    float inv = rsqrtf(red[0] / (float)H_ + 1e-6f);
    for (int i = tid; i < H_; i += 256) orow[i] = xr[i] * inv * w[i];
}

// ---------------- generic GEMM: C[M,N] = A[M,K] * B[N,K]^T (+bias[n]) (+res[m,n]) ----
// 64x64 tile, 4x4 f32x2 per thread, swizzled smem, global-load prefetch.
__global__ __launch_bounds__(256) void gemm_nt_kernel(
    const float* __restrict__ A, const float* __restrict__ B,
    const float* __restrict__ bias, const float* __restrict__ res,
    float* __restrict__ C, int M, int N, int K)
{
    __shared__ float As[16][64];
    __shared__ float Bs[16][64];
    int tid = threadIdx.x;
    int tx = tid & 15, ty = tid >> 4;
    int n0 = blockIdx.x * 64, m0 = blockIdx.y * 64;
    int lr = tid >> 2, lc = (tid & 3) * 4;
    int swc = lr ^ KSWZ(lc);
    const float* Ap = A + (size_t)(m0 + lr) * K + lc;
    const float* Bp = B + (size_t)(n0 + lr) * K + lc;
    ull_t acc2[4][2] = {};
    float4 a4 = *(const float4*)(Ap);
    float4 b4 = *(const float4*)(Bp);
    for (int k0 = 0; k0 < K; k0 += 16) {
        __syncthreads();
        As[lc+0][swc] = a4.x; As[lc+1][swc] = a4.y; As[lc+2][swc] = a4.z; As[lc+3][swc] = a4.w;
        Bs[lc+0][swc] = b4.x; Bs[lc+1][swc] = b4.y; Bs[lc+2][swc] = b4.z; Bs[lc+3][swc] = b4.w;
        __syncthreads();
        if (k0 + 16 < K) {
            a4 = *(const float4*)(Ap + k0 + 16);
            b4 = *(const float4*)(Bp + k0 + 16);
        }
#pragma unroll
        for (int kk = 0; kk < 16; ++kk) {
            int s = KSWZ(kk);
            float4 av = *(const float4*)&As[kk][(ty*4) ^ s];
            ull_t b0 = *(const ull_t*)&Bs[kk][(tx*4) ^ s];
            ull_t b1 = *(const ull_t*)&Bs[kk][((tx*4) ^ s) + 2];
            ull_t a0 = dup2(av.x), a1 = dup2(av.y), a2 = dup2(av.z), a3 = dup2(av.w);
            fma2(acc2[0][0], a0, b0); fma2(acc2[0][1], a0, b1);
            fma2(acc2[1][0], a1, b0); fma2(acc2[1][1], a1, b1);
            fma2(acc2[2][0], a2, b0); fma2(acc2[2][1], a2, b1);
            fma2(acc2[3][0], a3, b0); fma2(acc2[3][1], a3, b1);
        }
    }
#pragma unroll
    for (int i = 0; i < 4; ++i) {
        int m = m0 + ty*4 + i;
#pragma unroll
        for (int j2 = 0; j2 < 2; ++j2) {
            float2 p = unpack2(acc2[i][j2]);
            int n = n0 + tx*4 + j2*2;
            float v0 = p.x, v1 = p.y;
            if (bias) { v0 += bias[n]; v1 += bias[n+1]; }
            if (res)  { v0 += res[(size_t)m * N + n]; v1 += res[(size_t)m * N + n + 1]; }
            C[(size_t)m * N + n]     = v0;
            C[(size_t)m * N + n + 1] = v1;
        }
    }
}

// ---------------- RoPE (NeoX, full head dim, in place on q and k) ----------------
__global__ void rope_kernel(float* __restrict__ qkv, const int* __restrict__ pos)
{
    int t = blockIdx.x, head = blockIdx.y, d = threadIdx.x; // d in [0,64)
    float p = (float)pos[t];
    float inv = powf(1000000.f, -((float)(2 * d)) / 128.f);
    float ang = p * inv;
    float c = cosf(ang), s = sinf(ang);
    float* q = qkv + (size_t)t * QKVD + head * HD_;
    float* k = q + NH_ * HD_;
    float q1 = q[d], q2 = q[d + 64];
    q[d] = q1 * c - q2 * s;  q[d + 64] = q2 * c + q1 * s;
    float k1 = k[d], k2 = k[d + 64];
    k[d] = k1 * c - k2 * s;  k[d + 64] = k2 * c + k1 * s;
}

// ---------------- QK^T with causal mask + scale ----------------
__global__ __launch_bounds__(256) void qk_kernel(const float* __restrict__ qkv,
                                                 float* __restrict__ scores)
{
    int head = blockIdx.z;
    int n0 = blockIdx.x * 64, m0 = blockIdx.y * 64;
    if (n0 > m0) return;  // tile entirely above causal diagonal
    __shared__ float As[16][64];
    __shared__ float Bs[16][64];
    int tid = threadIdx.x;
    int tx = tid & 15, ty = tid >> 4;
    int lr = tid >> 2, lc = (tid & 3) * 4;
    int swc = lr ^ KSWZ(lc);
    const float* Ap = qkv + (size_t)(m0 + lr) * QKVD + head * HD_ + lc;
    const float* Bp = qkv + (size_t)(n0 + lr) * QKVD + NH_*HD_ + head * HD_ + lc;
    ull_t acc2[4][2] = {};
    float4 a4 = *(const float4*)(Ap);
    float4 b4 = *(const float4*)(Bp);
    for (int k0 = 0; k0 < HD_; k0 += 16) {
        __syncthreads();
        As[lc+0][swc] = a4.x; As[lc+1][swc] = a4.y; As[lc+2][swc] = a4.z; As[lc+3][swc] = a4.w;
        Bs[lc+0][swc] = b4.x; Bs[lc+1][swc] = b4.y; Bs[lc+2][swc] = b4.z; Bs[lc+3][swc] = b4.w;
        __syncthreads();
        if (k0 + 16 < HD_) {
            a4 = *(const float4*)(Ap + k0 + 16);
            b4 = *(const float4*)(Bp + k0 + 16);
        }
#pragma unroll
        for (int kk = 0; kk < 16; ++kk) {
            int s = KSWZ(kk);
            float4 av = *(const float4*)&As[kk][(ty*4) ^ s];
            ull_t b0 = *(const ull_t*)&Bs[kk][(tx*4) ^ s];
            ull_t b1 = *(const ull_t*)&Bs[kk][((tx*4) ^ s) + 2];
            ull_t a0 = dup2(av.x), a1 = dup2(av.y), a2 = dup2(av.z), a3 = dup2(av.w);
            fma2(acc2[0][0], a0, b0); fma2(acc2[0][1], a0, b1);
            fma2(acc2[1][0], a1, b0); fma2(acc2[1][1], a1, b1);
            fma2(acc2[2][0], a2, b0); fma2(acc2[2][1], a2, b1);
            fma2(acc2[3][0], a3, b0); fma2(acc2[3][1], a3, b1);
        }
    }
    const float scale = 0.08838834764831845f;
    float* sh = scores + (size_t)head * T_ * T_;
#pragma unroll
    for (int i = 0; i < 4; ++i) {
        int m = m0 + ty*4 + i;
#pragma unroll
        for (int j2 = 0; j2 < 2; ++j2) {
            float2 p = unpack2(acc2[i][j2]);
            int n = n0 + tx*4 + j2*2;
            sh[(size_t)m * T_ + n]     = (n     <= m) ? p.x * scale : -1e30f;
            sh[(size_t)m * T_ + n + 1] = (n + 1 <= m) ? p.y * scale : -1e30f;
        }
    }
}

// ---------------- row softmax (causal length i+1), zero-fill tail ----------------
__global__ void softmax_kernel(float* __restrict__ scores)
{
    int i = blockIdx.x, head = blockIdx.y;
    float* row = scores + (size_t)head * T_ * T_ + (size_t)i * T_;
    int L = i + 1;
    __shared__ float red[256];
    int tid = threadIdx.x;
    float mx = -1e30f;
    for (int j = tid; j < L; j += 256) mx = fmaxf(mx, row[j]);
    red[tid] = mx; __syncthreads();
    for (int o = 128; o > 0; o >>= 1) { if (tid < o) red[tid] = fmaxf(red[tid], red[tid+o]); __syncthreads(); }
    mx = red[0]; __syncthreads();
    float s = 0.f;
    for (int j = tid; j < L; j += 256) s += expf(row[j] - mx);
    red[tid] = s; __syncthreads();
    for (int o = 128; o > 0; o >>= 1) { if (tid < o) red[tid] += red[tid+o]; __syncthreads(); }
    float inv = 1.f / red[0];
    for (int j = tid; j < T_; j += 256)
        row[j] = (j < L) ? expf(row[j] - mx) * inv : 0.f;
}

// ---------------- P @ V  (NN, BN=128=HD), causal-truncated k loop ----------------
#define VSTRIDE 132
__global__ __launch_bounds__(256) void pv_kernel(const float* __restrict__ scores,
                                                 const float* __restrict__ qkv,
                                                 float* __restrict__ attn)
{
    int head = blockIdx.y;
    int m0 = blockIdx.x * 64;
    __shared__ float Ps[16][64];
    __shared__ float Vs[16][VSTRIDE];
    int tid = threadIdx.x;
    int tx = tid & 15, ty = tid >> 4;
    int lr = tid >> 2, lc = (tid & 3) * 4;
    int swc = lr ^ KSWZ(lc);
    int vr = tid >> 4, vc = (tid & 15) * 8;
    const float* P = scores + (size_t)head * T_ * T_;
    const float* Vb = qkv + 2 * NH_ * HD_ + head * HD_;
    ull_t acc2[4][4] = {};
    int jend = m0 + 64;
    float4 p4 = *(const float4*)(P + (size_t)(m0 + lr) * T_ + lc);
    float4 va = *(const float4*)(Vb + (size_t)vr * QKVD + vc);
    float4 vb = *(const float4*)(Vb + (size_t)vr * QKVD + vc + 4);
    for (int j0 = 0; j0 < jend; j0 += 16) {
        __syncthreads();
        Ps[lc+0][swc] = p4.x; Ps[lc+1][swc] = p4.y; Ps[lc+2][swc] = p4.z; Ps[lc+3][swc] = p4.w;
        *(float4*)&Vs[vr][vc]     = va;
        *(float4*)&Vs[vr][vc + 4] = vb;
        __syncthreads();
        if (j0 + 16 < jend) {
            p4 = *(const float4*)(P + (size_t)(m0 + lr) * T_ + j0 + 16 + lc);
            va = *(const float4*)(Vb + (size_t)(j0 + 16 + vr) * QKVD + vc);
            vb = *(const float4*)(Vb + (size_t)(j0 + 16 + vr) * QKVD + vc + 4);
        }
#pragma unroll
        for (int kk = 0; kk < 16; ++kk) {
            int s = KSWZ(kk);
            float4 av = *(const float4*)&Ps[kk][(ty*4) ^ s];
            ull_t b0 = *(const ull_t*)&Vs[kk][tx*8];
            ull_t b1 = *(const ull_t*)&Vs[kk][tx*8 + 2];
            ull_t b2 = *(const ull_t*)&Vs[kk][tx*8 + 4];
            ull_t b3 = *(const ull_t*)&Vs[kk][tx*8 + 6];
            ull_t a0 = dup2(av.x), a1 = dup2(av.y), a2 = dup2(av.z), a3 = dup2(av.w);
            fma2(acc2[0][0], a0, b0); fma2(acc2[0][1], a0, b1); fma2(acc2[0][2], a0, b2); fma2(acc2[0][3], a0, b3);
            fma2(acc2[1][0], a1, b0); fma2(acc2[1][1], a1, b1); fma2(acc2[1][2], a1, b2); fma2(acc2[1][3], a1, b3);
            fma2(acc2[2][0], a2, b0); fma2(acc2[2][1], a2, b1); fma2(acc2[2][2], a2, b2); fma2(acc2[2][3], a2, b3);
            fma2(acc2[3][0], a3, b0); fma2(acc2[3][1], a3, b1); fma2(acc2[3][2], a3, b2); fma2(acc2[3][3], a3, b3);
        }
    }
#pragma unroll
    for (int i = 0; i < 4; ++i) {
        int m = m0 + ty*4 + i;
#pragma unroll
        for (int j2 = 0; j2 < 4; ++j2) {
            float2 p = unpack2(acc2[i][j2]);
            attn[(size_t)m * H_ + head * HD_ + tx*8 + j2*2]     = p.x;
            attn[(size_t)m * H_ + head * HD_ + tx*8 + j2*2 + 1] = p.y;
        }
    }
}

// ---------------- router ----------------
__global__ void router_kernel(const float* __restrict__ h2, const float* __restrict__ gate_w,
                              const float* __restrict__ sg_w,
                              float* __restrict__ tw, int* __restrict__ ti,
                              float* __restrict__ sgl)
{
    int t = blockIdx.x;
    __shared__ float hs[H_];
    __shared__ float logits[E_];
    __shared__ float sgp[8];
    int tid = threadIdx.x;
    for (int i = tid; i < H_; i += 256) hs[i] = h2[(size_t)t * H_ + i];
    __syncthreads();
    int warp = tid >> 5, lane = tid & 31;
    for (int e = warp; e < E_; e += 8) {
        float s = 0.f;
        const float* w = gate_w + (size_t)e * H_;
        for (int i = lane; i < H_; i += 32) s += hs[i] * w[i];
        for (int o = 16; o > 0; o >>= 1) s += __shfl_xor_sync(~0u, s, o);
        if (lane == 0) logits[e] = s;
    }
    {
        float s = 0.f;
        for (int i = tid; i < H_; i += 256) s += hs[i] * sg_w[i];
        for (int o = 16; o > 0; o >>= 1) s += __shfl_xor_sync(~0u, s, o);
        if (lane == 0) sgp[warp] = s;
    }
    __syncthreads();
    if (tid == 0) {
        float sd = 0.f;
        for (int w = 0; w < 8; ++w) sd += sgp[w];
        sgl[t] = 1.f / (1.f + expf(-sd));
        float mx = -1e30f;
        for (int e = 0; e < E_; ++e) mx = fmaxf(mx, logits[e]);
        float p[E_]; float sum = 0.f;
        for (int e = 0; e < E_; ++e) { p[e] = expf(logits[e] - mx); sum += p[e]; }
        float inv = 1.f / sum;
        int idx[K_]; float val[K_]; float tot = 0.f;
        for (int k = 0; k < K_; ++k) {
            float best = -1.f; int bi = 0;
            for (int e = 0; e < E_; ++e) if (p[e] > best) { best = p[e]; bi = e; }
            idx[k] = bi; val[k] = best * inv; tot += val[k]; p[bi] = -2.f;
        }
        for (int k = 0; k < K_; ++k) { ti[t*K_ + k] = idx[k]; tw[t*K_ + k] = val[k] / tot; }
    }
}

// ---------------- expert routing bookkeeping ----------------
__global__ void zero_counts_kernel(int* cnt) { if (threadIdx.x < 64) cnt[threadIdx.x] = 0; }

__global__ void count_kernel(const int* __restrict__ ti, int* cnt)
{
    int i = blockIdx.x * 256 + threadIdx.x;
    if (i < NPAIR) atomicAdd(&cnt[ti[i]], 1);
}

__global__ void scan_kernel(const int* __restrict__ cnt, int* off, int* cur)
{
    if (threadIdx.x == 0) {
        int s = 0;
        for (int e = 0; e < E_; ++e) { off[e] = s; cur[e] = s; s += cnt[e]; }
        off[E_] = s;
    }
}

__global__ void scatter_kernel(const int* __restrict__ ti, const float* __restrict__ tw,
                               int* cur, int* __restrict__ tok, float* __restrict__ pw,
                               int* __restrict__ ppos)
{
    int i = blockIdx.x * 256 + threadIdx.x;
    if (i < NPAIR) {
        int e = ti[i];
        int pos = atomicAdd(&cur[e], 1);
        tok[pos] = i >> 2;
        pw[pos] = tw[i];
        ppos[i] = pos;
    }
}

// ---------------- routed experts: fused gate/up GEMM + silu*u ----------------
__global__ __launch_bounds__(256) void expert_gateup_kernel(
    const float* __restrict__ h2, const float* __restrict__ Wg_all,
    const float* __restrict__ Wu_all, const int* __restrict__ cnt,
    const int* __restrict__ off, const int* __restrict__ tok,
    float* __restrict__ act)
{
    int e = blockIdx.y;
    int n0 = blockIdx.x * 64;
    int M = cnt[e], base = off[e];
    const float* Wg = Wg_all + (size_t)e * I_ * H_;
    const float* Wu = Wu_all + (size_t)e * I_ * H_;
    __shared__ float As[16][64];
    __shared__ float Gs[16][64];
    __shared__ float Us[16][64];
    int tid = threadIdx.x;
    int tx = tid & 15, ty = tid >> 4;
    int lr = tid >> 2, lc = (tid & 3) * 4;
    int swc = lr ^ KSWZ(lc);
    const float* Gp = Wg + (size_t)(n0 + lr) * H_ + lc;
    const float* Up = Wu + (size_t)(n0 + lr) * H_ + lc;
    for (int m0 = 0; m0 < M; m0 += 64) {
        int arow = m0 + lr;
        int tk = tok[base + ((arow < M) ? arow : 0)];   // clamp; invalid rows never stored
        const float* Ap = h2 + (size_t)tk * H_ + lc;
        ull_t ag2[4][2] = {}, au2[4][2] = {};
        float4 a4 = *(const float4*)(Ap);
        float4 g4 = *(const float4*)(Gp);
        float4 u4 = *(const float4*)(Up);
        for (int k0 = 0; k0 < H_; k0 += 16) {
            __syncthreads();
            As[lc+0][swc] = a4.x; As[lc+1][swc] = a4.y; As[lc+2][swc] = a4.z; As[lc+3][swc] = a4.w;
            Gs[lc+0][swc] = g4.x; Gs[lc+1][swc] = g4.y; Gs[lc+2][swc] = g4.z; Gs[lc+3][swc] = g4.w;
            Us[lc+0][swc] = u4.x; Us[lc+1][swc] = u4.y; Us[lc+2][swc] = u4.z; Us[lc+3][swc] = u4.w;
            __syncthreads();
            if (k0 + 16 < H_) {
                a4 = *(const float4*)(Ap + k0 + 16);
                g4 = *(const float4*)(Gp + k0 + 16);
                u4 = *(const float4*)(Up + k0 + 16);
            }
#pragma unroll
            for (int kk = 0; kk < 16; ++kk) {
                int s = KSWZ(kk);
                float4 av = *(const float4*)&As[kk][(ty*4) ^ s];
                ull_t gb0 = *(const ull_t*)&Gs[kk][(tx*4) ^ s];
                ull_t gb1 = *(const ull_t*)&Gs[kk][((tx*4) ^ s) + 2];
                ull_t ub0 = *(const ull_t*)&Us[kk][(tx*4) ^ s];
                ull_t ub1 = *(const ull_t*)&Us[kk][((tx*4) ^ s) + 2];
                ull_t a0 = dup2(av.x), a1 = dup2(av.y), a2 = dup2(av.z), a3 = dup2(av.w);
                fma2(ag2[0][0], a0, gb0); fma2(ag2[0][1], a0, gb1);
                fma2(ag2[1][0], a1, gb0); fma2(ag2[1][1], a1, gb1);
                fma2(ag2[2][0], a2, gb0); fma2(ag2[2][1], a2, gb1);
                fma2(ag2[3][0], a3, gb0); fma2(ag2[3][1], a3, gb1);
                fma2(au2[0][0], a0, ub0); fma2(au2[0][1], a0, ub1);
                fma2(au2[1][0], a1, ub0); fma2(au2[1][1], a1, ub1);
                fma2(au2[2][0], a2, ub0); fma2(au2[2][1], a2, ub1);
                fma2(au2[3][0], a3, ub0); fma2(au2[3][1], a3, ub1);
            }
        }
#pragma unroll
        for (int i = 0; i < 4; ++i) {
            int row = m0 + ty*4 + i;
            if (row < M) {
#pragma unroll
                for (int j2 = 0; j2 < 2; ++j2) {
                    float2 g = unpack2(ag2[i][j2]);
                    float2 u = unpack2(au2[i][j2]);
                    float s0 = g.x / (1.f + expf(-g.x));
                    float s1 = g.y / (1.f + expf(-g.y));
                    act[(size_t)(base + row) * I_ + n0 + tx*4 + j2*2]     = s0 * u.x;
                    act[(size_t)(base + row) * I_ + n0 + tx*4 + j2*2 + 1] = s1 * u.y;
                }
            }
        }
    }
}

// ---------------- routed experts: down projection, scaled by combine weight ----
__global__ __launch_bounds__(256) void expert_down_kernel(
    const float* __restrict__ act, const float* __restrict__ Wd_all,
    const int* __restrict__ cnt, const int* __restrict__ off,
    const float* __restrict__ pw, float* __restrict__ dexp)
{
    int e = blockIdx.y;
    int n0 = blockIdx.x * 64;
    int M = cnt[e], base = off[e];
    const float* Wd = Wd_all + (size_t)e * H_ * I_;
    const float* A = act + (size_t)base * I_;
    __shared__ float As[16][64];
    __shared__ float Bs[16][64];
    int tid = threadIdx.x;
    int tx = tid & 15, ty = tid >> 4;
    int lr = tid >> 2, lc = (tid & 3) * 4;
    int swc = lr ^ KSWZ(lc);
    const float* Bp = Wd + (size_t)(n0 + lr) * I_ + lc;
    for (int m0 = 0; m0 < M; m0 += 64) {
        int arow = m0 + lr;
        const float* Ap = A + (size_t)((arow < M) ? arow : 0) * I_ + lc;
        ull_t acc2[4][2] = {};
        float4 a4 = *(const float4*)(Ap);
        float4 b4 = *(const float4*)(Bp);
        for (int k0 = 0; k0 < I_; k0 += 16) {
            __syncthreads();
            As[lc+0][swc] = a4.x; As[lc+1][swc] = a4.y; As[lc+2][swc] = a4.z; As[lc+3][swc] = a4.w;
            Bs[lc+0][swc] = b4.x; Bs[lc+1][swc] = b4.y; Bs[lc+2][swc] = b4.z; Bs[lc+3][swc] = b4.w;
            __syncthreads();
            if (k0 + 16 < I_) {
                a4 = *(const float4*)(Ap + k0 + 16);
                b4 = *(const float4*)(Bp + k0 + 16);
            }
#pragma unroll
            for (int kk = 0; kk < 16; ++kk) {
                int s = KSWZ(kk);
                float4 av = *(const float4*)&As[kk][(ty*4) ^ s];
                ull_t b0 = *(const ull_t*)&Bs[kk][(tx*4) ^ s];
                ull_t b1 = *(const ull_t*)&Bs[kk][((tx*4) ^ s) + 2];
                ull_t a0 = dup2(av.x), a1 = dup2(av.y), a2 = dup2(av.z), a3 = dup2(av.w);
                fma2(acc2[0][0], a0, b0); fma2(acc2[0][1], a0, b1);
                fma2(acc2[1][0], a1, b0); fma2(acc2[1][1], a1, b1);
                fma2(acc2[2][0], a2, b0); fma2(acc2[2][1], a2, b1);
                fma2(acc2[3][0], a3, b0); fma2(acc2[3][1], a3, b1);
            }
        }
#pragma unroll
        for (int i = 0; i < 4; ++i) {
            int row = m0 + ty*4 + i;
            if (row < M) {
                float w = pw[base + row];
#pragma unroll
                for (int j2 = 0; j2 < 2; ++j2) {
                    float2 p = unpack2(acc2[i][j2]);
                    dexp[(size_t)(base + row) * H_ + n0 + tx*4 + j2*2]     = p.x * w;
                    dexp[(size_t)(base + row) * H_ + n0 + tx*4 + j2*2 + 1] = p.y * w;
                }
            }
        }
    }
}

// ---------------- shared expert: fused gate/up GEMM + silu*u (dense) ----------
__global__ __launch_bounds__(256) void shared_gateup_kernel(
    const float* __restrict__ h2, const float* __restrict__ Wg,
    const float* __restrict__ Wu, float* __restrict__ sact)
{
    int n0 = blockIdx.x * 64;
    int m0 = blockIdx.y * 64;
    __shared__ float As[16][64];
    __shared__ float Gs[16][64];
    __shared__ float Us[16][64];
    int tid = threadIdx.x;
    int tx = tid & 15, ty = tid >> 4;
    int lr = tid >> 2, lc = (tid & 3) * 4;
    int swc = lr ^ KSWZ(lc);
    const float* Ap = h2 + (size_t)(m0 + lr) * H_ + lc;
    const float* Gp = Wg + (size_t)(n0 + lr) * H_ + lc;
    const float* Up = Wu + (size_t)(n0 + lr) * H_ + lc;
    ull_t ag2[4][2] = {}, au2[4][2] = {};
    float4 a4 = *(const float4*)(Ap);
    float4 g4 = *(const float4*)(Gp);
    float4 u4 = *(const float4*)(Up);
    for (int k0 = 0; k0 < H_; k0 += 16) {
        __syncthreads();
        As[lc+0][swc] = a4.x; As[lc+1][swc] = a4.y; As[lc+2][swc] = a4.z; As[lc+3][swc] = a4.w;
        Gs[lc+0][swc] = g4.x; Gs[lc+1][swc] = g4.y; Gs[lc+2][swc] = g4.z; Gs[lc+3][swc] = g4.w;
        Us[lc+0][swc] = u4.x; Us[lc+1][swc] = u4.y; Us[lc+2][swc] = u4.z; Us[lc+3][swc] = u4.w;
        __syncthreads();
        if (k0 + 16 < H_) {
            a4 = *(const float4*)(Ap + k0 + 16);
            g4 = *(const float4*)(Gp + k0 + 16);
            u4 = *(const float4*)(Up + k0 + 16);
        }
#pragma unroll
        for (int kk = 0; kk < 16; ++kk) {
            int s = KSWZ(kk);
            float4 av = *(const float4*)&As[kk][(ty*4) ^ s];
            ull_t gb0 = *(const ull_t*)&Gs[kk][(tx*4) ^ s];
            ull_t gb1 = *(const ull_t*)&Gs[kk][((tx*4) ^ s) + 2];
            ull_t ub0 = *(const ull_t*)&Us[kk][(tx*4) ^ s];
            ull_t ub1 = *(const ull_t*)&Us[kk][((tx*4) ^ s) + 2];
            ull_t a0 = dup2(av.x), a1 = dup2(av.y), a2 = dup2(av.z), a3 = dup2(av.w);
            fma2(ag2[0][0], a0, gb0); fma2(ag2[0][1], a0, gb1);
            fma2(ag2[1][0], a1, gb0); fma2(ag2[1][1], a1, gb1);
            fma2(ag2[2][0], a2, gb0); fma2(ag2[2][1], a2, gb1);
            fma2(ag2[3][0], a3, gb0); fma2(ag2[3][1], a3, gb1);
            fma2(au2[0][0], a0, ub0); fma2(au2[0][1], a0, ub1);
            fma2(au2[1][0], a1, ub0); fma2(au2[1][1], a1, ub1);
            fma2(au2[2][0], a2, ub0); fma2(au2[2][1], a2, ub1);
            fma2(au2[3][0], a3, ub0); fma2(au2[3][1], a3, ub1);
        }
    }
#pragma unroll
    for (int i = 0; i < 4; ++i) {
        int row = m0 + ty*4 + i;
#pragma unroll
        for (int j2 = 0; j2 < 2; ++j2) {
            float2 g = unpack2(ag2[i][j2]);
            float2 u = unpack2(au2[i][j2]);
            float s0 = g.x / (1.f + expf(-g.x));
            float s1 = g.y / (1.f + expf(-g.y));
            sact[(size_t)row * SI_ + n0 + tx*4 + j2*2]     = s0 * u.x;
            sact[(size_t)row * SI_ + n0 + tx*4 + j2*2 + 1] = s1 * u.y;
        }
    }
}

// ---------------- final combine: residual + gated shared + 4 routed pairs ------
__global__ void combine_kernel(const float* __restrict__ x1, const float* __restrict__ so,
                               const float* __restrict__ sgl, const float* __restrict__ dexp,
                               const int* __restrict__ ppos, float* __restrict__ out)
{
    int t = blockIdx.x;
    float g = sgl[t];
    int p0 = ppos[t*K_ + 0], p1 = ppos[t*K_ + 1], p2 = ppos[t*K_ + 2], p3 = ppos[t*K_ + 3];
    for (int h = threadIdx.x; h < H_; h += 256) {
        float v = x1[(size_t)t*H_ + h] + g * so[(size_t)t*H_ + h];
        v += dexp[(size_t)p0*H_ + h];
        v += dexp[(size_t)p1*H_ + h];
        v += dexp[(size_t)p2*H_ + h];
        v += dexp[(size_t)p3*H_ + h];
        out[(size_t)t*H_ + h] = v;
    }
}

// ---------------- launch ----------------
template <typename Tp>
static Tp* sym_addr(const void* symbol)
{
    void* p = nullptr;
    cudaGetSymbolAddress(&p, symbol);
    return (Tp*)p;
}

extern "C" void kernel_launch(void* const* d_in, const int* in_sizes, int n_in,
                              void* d_out, int out_size)
{
    const int*   positions = (const int*)  d_in[0];
    const float* x         = (const float*)d_in[1];
    const float* ln1_w     = (const float*)d_in[2];
    const float* ln2_w     = (const float*)d_in[3];
    const float* Wqkv      = (const float*)d_in[4];
    const float* bqkv      = (const float*)d_in[5];
    const float* Wo        = (const float*)d_in[6];
    const float* gate_w    = (const float*)d_in[7];
    const float* W_gate    = (const float*)d_in[8];
    const float* W_up      = (const float*)d_in[9];
    const float* W_down    = (const float*)d_in[10];
    const float* Ws_gate   = (const float*)d_in[11];
    const float* Ws_up     = (const float*)d_in[12];
    const float* Ws_down   = (const float*)d_in[13];
    const float* sg_w      = (const float*)d_in[14];
    float* out = (float*)d_out;

    float* h1   = sym_addr<float>(g_h1);
    float* qkv  = sym_addr<float>(g_qkv);
    float* sc   = sym_addr<float>(g_scores);
    float* attn = sym_addr<float>(g_attn);
    float* x1   = sym_addr<float>(g_x1);
    float* h2   = sym_addr<float>(g_h2);
    float* tw   = sym_addr<float>(g_tw);
    int*   ti   = sym_addr<int>(g_ti);
    int*   cnt  = sym_addr<int>(g_cnt);
    int*   off  = sym_addr<int>(g_off);
    int*   cur  = sym_addr<int>(g_cur);
    int*   tok  = sym_addr<int>(g_tok);
    float* pw   = sym_addr<float>(g_pw);
    int*   ppos = sym_addr<int>(g_ppos);
    float* act  = sym_addr<float>(g_act);
    float* dexp = sym_addr<float>(g_dexp);
    float* sact = sym_addr<float>(g_sact);
    float* so   = sym_addr<float>(g_so);
    float* sgl  = sym_addr<float>(g_sgl);

    // ---- attention ----
    rmsnorm_kernel<<<T_, 256>>>(x, ln1_w, h1);
    gemm_nt_kernel<<<dim3(QKVD/64, T_/64), 256>>>(h1, Wqkv, bqkv, nullptr, qkv, T_, QKVD, H_);
    rope_kernel<<<dim3(T_, NH_), 64>>>(qkv, positions);
    qk_kernel<<<dim3(T_/64, T_/64, NH_), 256>>>(qkv, sc);
    softmax_kernel<<<dim3(T_, NH_), 256>>>(sc);
    pv_kernel<<<dim3(T_/64, NH_), 256>>>(sc, qkv, attn);
    gemm_nt_kernel<<<dim3(H_/64, T_/64), 256>>>(attn, Wo, nullptr, x, x1, T_, H_, H_);

    // ---- MoE ----
    rmsnorm_kernel<<<T_, 256>>>(x1, ln2_w, h2);
    router_kernel<<<T_, 256>>>(h2, gate_w, sg_w, tw, ti, sgl);
    zero_counts_kernel<<<1, 64>>>(cnt);
    count_kernel<<<NPAIR/256, 256>>>(ti, cnt);
    scan_kernel<<<1, 32>>>(cnt, off, cur);
    scatter_kernel<<<NPAIR/256, 256>>>(ti, tw, cur, tok, pw, ppos);
    expert_gateup_kernel<<<dim3(I_/64, E_), 256>>>(h2, W_gate, W_up, cnt, off, tok, act);
    expert_down_kernel<<<dim3(H_/64, E_), 256>>>(act, W_down, cnt, off, pw, dexp);
    shared_gateup_kernel<<<dim3(SI_/64, T_/64), 256>>>(h2, Ws_gate, Ws_up, sact);
    gemm_nt_kernel<<<dim3(H_/64, T_/64), 256>>>(sact, Ws_down, nullptr, nullptr, so, T_, H_, SI_);
    combine_kernel<<<T_, 256>>>(x1, so, sgl, dexp, ppos, out);
}

// round 14
// speedup vs baseline: 1.4513x; 1.0177x over previous
#include <cuda_runtime.h>
#include <math.h>

// ---------------- problem constants ----------------
#define T_   1024            // tokens (B*S)
#define H_   2048            // hidden
#define NH_  16
#define HD_  128
#define E_   60
#define K_   4
#define I_   1408
#define SI_  5632
#define QKVD 6144            // 3*NH*HD
#define NPAIR (T_*K_)        // 4096

typedef unsigned long long ull_t;

// packed f32x2 helpers (sm_103a dual-rate fp32 FMA)
__device__ __forceinline__ ull_t dup2(float x) {
    ull_t r; unsigned u = __float_as_uint(x);
    asm("mov.b64 %0, {%1, %1};" : "=l"(r) : "r"(u));
    return r;
}
__device__ __forceinline__ void fma2(ull_t& acc, ull_t a, ull_t b) {
    asm("fma.rn.f32x2 %0, %1, %2, %0;" : "+l"(acc) : "l"(a), "l"(b));
}
__device__ __forceinline__ float2 unpack2(ull_t v) {
    float2 f;
    asm("mov.b64 {%0, %1}, %2;" : "=f"(f.x), "=f"(f.y) : "l"(v));
    return f;
}

// XOR swizzle for transposed [k][m] shared tiles (k-depth 16):
// element (k,m) stored at column m ^ (((k>>2)&3)*8). Conflict-free scalar
// stores and conflict-free 16B/8B loads (kk is an unroll constant).
#define KSWZ(k)  ((((k) >> 2) & 3) * 8)

// ---------------- scratch (device globals; no allocs allowed) ----------------
__device__ float g_h1 [T_*H_];
__device__ float g_qkv[(size_t)T_*QKVD];
__device__ float g_scores[(size_t)NH_*T_*T_];
__device__ float g_attn[T_*H_];
__device__ float g_x1 [T_*H_];
__device__ float g_h2 [T_*H_];
__device__ float g_tw [NPAIR];
__device__ int   g_ti [NPAIR];
__device__ int   g_cnt[64];
__device__ int   g_off[64];
__device__ int   g_cur[64];
__device__ int   g_tok[NPAIR];
__device__ float g_pw [NPAIR];
__device__ int   g_ppos[NPAIR];
__device__ float g_act [(size_t)NPAIR*I_];
__device__ float g_dexp[(size_t)NPAIR*H_];
__device__ float g_sact[(size_t)T_*SI_];
__device__ float g_sg  [(size_t)T_*SI_];
__device__ float g_so  [T_*H_];
__device__ float g_sgl [T_];

// ---------------- rmsnorm ----------------
__global__ void rmsnorm_kernel(const float* __restrict__ x, const float* __restrict__ w,
                               float* __restrict__ out)
{
    int t = blockIdx.x;
    const float* xr = x + (size_t)t * H_;
    float* orow = out + (size_t)t * H_;
    __shared__ float red[256];
    int tid = threadIdx.x;
    float s = 0.f;
    for (int i = tid; i < H_; i += 256) { float v = xr[i]; s += v * v; }
    red[tid] = s; __syncthreads();
    for (int o = 128; o > 0; o >>= 1) { if (tid < o) red[tid] += red[tid + o]; __syncthreads(); }
    float inv = rsqrtf(red[0] / (float)H_ + 1e-6f);
    for (int i = tid; i < H_; i += 256) orow[i] = xr[i] * inv * w[i];
}

// ======== dense GEMM, M-tile 128 x N-tile 64, 8x4 per thread ========
// C[M,N] = A[M,K]*B[N,K]^T; optional bias[n], res[m,n] added; optional
// glu[m,n]: C = silu(glu)*acc (for the shared-expert up pass).
// M%128==0, N%64==0, K%16==0.
__global__ __launch_bounds__(256) void gemm_nt_mt128_kernel(
    const float* __restrict__ A, const float* __restrict__ B,
    const float* __restrict__ bias, const float* __restrict__ res,
    const float* __restrict__ glu, float* __restrict__ C,
    int M, int N, int K)
{
    __shared__ float As[16][128];
    __shared__ float Bs[16][64];
    int tid = threadIdx.x;
    int tx = tid & 15, ty = tid >> 4;       // compute: rows ty*8.., cols tx*4..
    int n0 = blockIdx.x * 64, m0 = blockIdx.y * 128;
    int ar = tid >> 1, ac = (tid & 1) * 8;  // A load: row ar, k ac..ac+7
    int br = tid >> 2, bc = (tid & 3) * 4;  // B load: row br, k bc..bc+3
    int bswc = br ^ KSWZ(bc);
    const float* Ap = A + (size_t)(m0 + ar) * K + ac;
    const float* Bp = B + (size_t)(n0 + br) * K + bc;
    ull_t acc[8][2] = {};
    float4 a40 = *(const float4*)(Ap);
    float4 a41 = *(const float4*)(Ap + 4);
    float4 b4  = *(const float4*)(Bp);
    for (int k0 = 0; k0 < K; k0 += 16) {
        float av[8] = {a40.x,a40.y,a40.z,a40.w,a41.x,a41.y,a41.z,a41.w};
        __syncthreads();
#pragma unroll
        for (int i = 0; i < 8; ++i) {
            int k = ac + i;
            As[k][ar ^ KSWZ(k)] = av[i];
        }
        Bs[bc+0][bswc] = b4.x; Bs[bc+1][bswc] = b4.y; Bs[bc+2][bswc] = b4.z; Bs[bc+3][bswc] = b4.w;
        __syncthreads();
        if (k0 + 16 < K) {
            a40 = *(const float4*)(Ap + k0 + 16);
            a41 = *(const float4*)(Ap + k0 + 20);
            b4  = *(const float4*)(Bp + k0 + 16);
        }
#pragma unroll
        for (int kk = 0; kk < 16; ++kk) {
            int s = KSWZ(kk);
            int acol = (ty*8) ^ s;
            float4 av0 = *(const float4*)&As[kk][acol];
            float4 av1 = *(const float4*)&As[kk][acol + 4];
            ull_t b0 = *(const ull_t*)&Bs[kk][(tx*4) ^ s];
            ull_t b1 = *(const ull_t*)&Bs[kk][((tx*4) ^ s) + 2];
            ull_t a0 = dup2(av0.x), a1 = dup2(av0.y), a2 = dup2(av0.z), a3 = dup2(av0.w);
            ull_t a4 = dup2(av1.x), a5 = dup2(av1.y), a6 = dup2(av1.z), a7 = dup2(av1.w);
            fma2(acc[0][0], a0, b0); fma2(acc[0][1], a0, b1);
            fma2(acc[1][0], a1, b0); fma2(acc[1][1], a1, b1);
            fma2(acc[2][0], a2, b0); fma2(acc[2][1], a2, b1);
            fma2(acc[3][0], a3, b0); fma2(acc[3][1], a3, b1);
            fma2(acc[4][0], a4, b0); fma2(acc[4][1], a4, b1);
            fma2(acc[5][0], a5, b0); fma2(acc[5][1], a5, b1);
            fma2(acc[6][0], a6, b0); fma2(acc[6][1], a6, b1);
            fma2(acc[7][0], a7, b0); fma2(acc[7][1], a7, b1);
        }
    }
#pragma unroll
    for (int i = 0; i < 8; ++i) {
        int m = m0 + ty*8 + i;
#pragma unroll
        for (int j2 = 0; j2 < 2; ++j2) {
            float2 p = unpack2(acc[i][j2]);
            int n = n0 + tx*4 + j2*2;
            if (bias) { p.x += bias[n]; p.y += bias[n+1]; }
            if (res)  { p.x += res[(size_t)m*N + n]; p.y += res[(size_t)m*N + n + 1]; }
            if (glu) {
                float g0 = glu[(size_t)m*N + n], g1 = glu[(size_t)m*N + n + 1];
                p.x *= g0 / (1.f + expf(-g0));
                p.y *= g1 / (1.f + expf(-g1));
            }
            C[(size_t)m*N + n]     = p.x;
            C[(size_t)m*N + n + 1] = p.y;
        }
    }
}

// ---------------- RoPE (NeoX, full head dim, in place on q and k) ----------------
__global__ void rope_kernel(float* __restrict__ qkv, const int* __restrict__ pos)
{
    int t = blockIdx.x, head = blockIdx.y, d = threadIdx.x; // d in [0,64)
    float p = (float)pos[t];
    float inv = powf(1000000.f, -((float)(2 * d)) / 128.f);
    float ang = p * inv;
    float c = cosf(ang), s = sinf(ang);
    float* q = qkv + (size_t)t * QKVD + head * HD_;
    float* k = q + NH_ * HD_;
    float q1 = q[d], q2 = q[d + 64];
    q[d] = q1 * c - q2 * s;  q[d + 64] = q2 * c + q1 * s;
    float k1 = k[d], k2 = k[d + 64];
    k[d] = k1 * c - k2 * s;  k[d + 64] = k2 * c + k1 * s;
}

// ---------------- QK^T with causal mask + scale ----------------
__global__ __launch_bounds__(256) void qk_kernel(const float* __restrict__ qkv,
                                                 float* __restrict__ scores)
{
    int head = blockIdx.z;
    int n0 = blockIdx.x * 64, m0 = blockIdx.y * 64;
    if (n0 > m0) return;  // tile entirely above causal diagonal
    __shared__ float As[16][64];
    __shared__ float Bs[16][64];
    int tid = threadIdx.x;
    int tx = tid & 15, ty = tid >> 4;
    int lr = tid >> 2, lc = (tid & 3) * 4;
    int swc = lr ^ KSWZ(lc);
    const float* Ap = qkv + (size_t)(m0 + lr) * QKVD + head * HD_ + lc;
    const float* Bp = qkv + (size_t)(n0 + lr) * QKVD + NH_*HD_ + head * HD_ + lc;
    ull_t acc2[4][2] = {};
    float4 a4 = *(const float4*)(Ap);
    float4 b4 = *(const float4*)(Bp);
    for (int k0 = 0; k0 < HD_; k0 += 16) {
        __syncthreads();
        As[lc+0][swc] = a4.x; As[lc+1][swc] = a4.y; As[lc+2][swc] = a4.z; As[lc+3][swc] = a4.w;
        Bs[lc+0][swc] = b4.x; Bs[lc+1][swc] = b4.y; Bs[lc+2][swc] = b4.z; Bs[lc+3][swc] = b4.w;
        __syncthreads();
        if (k0 + 16 < HD_) {
            a4 = *(const float4*)(Ap + k0 + 16);
            b4 = *(const float4*)(Bp + k0 + 16);
        }
#pragma unroll
        for (int kk = 0; kk < 16; ++kk) {
            int s = KSWZ(kk);
            float4 av = *(const float4*)&As[kk][(ty*4) ^ s];
            ull_t b0 = *(const ull_t*)&Bs[kk][(tx*4) ^ s];
            ull_t b1 = *(const ull_t*)&Bs[kk][((tx*4) ^ s) + 2];
            ull_t a0 = dup2(av.x), a1 = dup2(av.y), a2 = dup2(av.z), a3 = dup2(av.w);
            fma2(acc2[0][0], a0, b0); fma2(acc2[0][1], a0, b1);
            fma2(acc2[1][0], a1, b0); fma2(acc2[1][1], a1, b1);
            fma2(acc2[2][0], a2, b0); fma2(acc2[2][1], a2, b1);
            fma2(acc2[3][0], a3, b0); fma2(acc2[3][1], a3, b1);
        }
    }
    const float scale = 0.08838834764831845f;
    float* sh = scores + (size_t)head * T_ * T_;
#pragma unroll
    for (int i = 0; i < 4; ++i) {
        int m = m0 + ty*4 + i;
#pragma unroll
        for (int j2 = 0; j2 < 2; ++j2) {
            float2 p = unpack2(acc2[i][j2]);
            int n = n0 + tx*4 + j2*2;
            sh[(size_t)m * T_ + n]     = (n     <= m) ? p.x * scale : -1e30f;
            sh[(size_t)m * T_ + n + 1] = (n + 1 <= m) ? p.y * scale : -1e30f;
        }
    }
}

// ---------------- row softmax (causal length i+1), zero-fill tail ----------------
__global__ void softmax_kernel(float* __restrict__ scores)
{
    int i = blockIdx.x, head = blockIdx.y;
    float* row = scores + (size_t)head * T_ * T_ + (size_t)i * T_;
    int L = i + 1;
    __shared__ float red[256];
    int tid = threadIdx.x;
    float mx = -1e30f;
    for (int j = tid; j < L; j += 256) mx = fmaxf(mx, row[j]);
    red[tid] = mx; __syncthreads();
    for (int o = 128; o > 0; o >>= 1) { if (tid < o) red[tid] = fmaxf(red[tid], red[tid+o]); __syncthreads(); }
    mx = red[0]; __syncthreads();
    float s = 0.f;
    for (int j = tid; j < L; j += 256) s += expf(row[j] - mx);
    red[tid] = s; __syncthreads();
    for (int o = 128; o > 0; o >>= 1) { if (tid < o) red[tid] += red[tid+o]; __syncthreads(); }
    float inv = 1.f / red[0];
    for (int j = tid; j < T_; j += 256)
        row[j] = (j < L) ? expf(row[j] - mx) * inv : 0.f;
}

// ---------------- P @ V  (NN, BN=128=HD), causal-truncated k loop ----------------
#define VSTRIDE 132
__global__ __launch_bounds__(256) void pv_kernel(const float* __restrict__ scores,
                                                 const float* __restrict__ qkv,
                                                 float* __restrict__ attn)
{
    int head = blockIdx.y;
    int m0 = blockIdx.x * 64;
    __shared__ float Ps[16][64];
    __shared__ float Vs[16][VSTRIDE];
    int tid = threadIdx.x;
    int tx = tid & 15, ty = tid >> 4;
    int lr = tid >> 2, lc = (tid & 3) * 4;
    int swc = lr ^ KSWZ(lc);
    int vr = tid >> 4, vc = (tid & 15) * 8;
    const float* P = scores + (size_t)head * T_ * T_;
    const float* Vb = qkv + 2 * NH_ * HD_ + head * HD_;
    ull_t acc2[4][4] = {};
    int jend = m0 + 64;
    float4 p4 = *(const float4*)(P + (size_t)(m0 + lr) * T_ + lc);
    float4 va = *(const float4*)(Vb + (size_t)vr * QKVD + vc);
    float4 vb = *(const float4*)(Vb + (size_t)vr * QKVD + vc + 4);
    for (int j0 = 0; j0 < jend; j0 += 16) {
        __syncthreads();
        Ps[lc+0][swc] = p4.x; Ps[lc+1][swc] = p4.y; Ps[lc+2][swc] = p4.z; Ps[lc+3][swc] = p4.w;
        *(float4*)&Vs[vr][vc]     = va;
        *(float4*)&Vs[vr][vc + 4] = vb;
        __syncthreads();
        if (j0 + 16 < jend) {
            p4 = *(const float4*)(P + (size_t)(m0 + lr) * T_ + j0 + 16 + lc);
            va = *(const float4*)(Vb + (size_t)(j0 + 16 + vr) * QKVD + vc);
            vb = *(const float4*)(Vb + (size_t)(j0 + 16 + vr) * QKVD + vc + 4);
        }
#pragma unroll
        for (int kk = 0; kk < 16; ++kk) {
            int s = KSWZ(kk);
            float4 av = *(const float4*)&Ps[kk][(ty*4) ^ s];
            ull_t b0 = *(const ull_t*)&Vs[kk][tx*8];
            ull_t b1 = *(const ull_t*)&Vs[kk][tx*8 + 2];
            ull_t b2 = *(const ull_t*)&Vs[kk][tx*8 + 4];
            ull_t b3 = *(const ull_t*)&Vs[kk][tx*8 + 6];
            ull_t a0 = dup2(av.x), a1 = dup2(av.y), a2 = dup2(av.z), a3 = dup2(av.w);
            fma2(acc2[0][0], a0, b0); fma2(acc2[0][1], a0, b1); fma2(acc2[0][2], a0, b2); fma2(acc2[0][3], a0, b3);
            fma2(acc2[1][0], a1, b0); fma2(acc2[1][1], a1, b1); fma2(acc2[1][2], a1, b2); fma2(acc2[1][3], a1, b3);
            fma2(acc2[2][0], a2, b0); fma2(acc2[2][1], a2, b1); fma2(acc2[2][2], a2, b2); fma2(acc2[2][3], a2, b3);
            fma2(acc2[3][0], a3, b0); fma2(acc2[3][1], a3, b1); fma2(acc2[3][2], a3, b2); fma2(acc2[3][3], a3, b3);
        }
    }
#pragma unroll
    for (int i = 0; i < 4; ++i) {
        int m = m0 + ty*4 + i;
#pragma unroll
        for (int j2 = 0; j2 < 4; ++j2) {
            float2 p = unpack2(acc2[i][j2]);
            attn[(size_t)m * H_ + head * HD_ + tx*8 + j2*2]     = p.x;
            attn[(size_t)m * H_ + head * HD_ + tx*8 + j2*2 + 1] = p.y;
        }
    }
}

// ---------------- router ----------------
__global__ void router_kernel(const float* __restrict__ h2, const float* __restrict__ gate_w,
                              const float* __restrict__ sg_w,
                              float* __restrict__ tw, int* __restrict__ ti,
                              float* __restrict__ sgl)
{
    int t = blockIdx.x;
    __shared__ float hs[H_];
    __shared__ float logits[E_];
    __shared__ float sgp[8];
    int tid = threadIdx.x;
    for (int i = tid; i < H_; i += 256) hs[i] = h2[(size_t)t * H_ + i];
    __syncthreads();
    int warp = tid >> 5, lane = tid & 31;
    for (int e = warp; e < E_; e += 8) {
        float s = 0.f;
        const float* w = gate_w + (size_t)e * H_;
        for (int i = lane; i < H_; i += 32) s += hs[i] * w[i];
        for (int o = 16; o > 0; o >>= 1) s += __shfl_xor_sync(~0u, s, o);
        if (lane == 0) logits[e] = s;
    }
    {
        float s = 0.f;
        for (int i = tid; i < H_; i += 256) s += hs[i] * sg_w[i];
        for (int o = 16; o > 0; o >>= 1) s += __shfl_xor_sync(~0u, s, o);
        if (lane == 0) sgp[warp] = s;
    }
    __syncthreads();
    if (tid == 0) {
        float sd = 0.f;
        for (int w = 0; w < 8; ++w) sd += sgp[w];
        sgl[t] = 1.f / (1.f + expf(-sd));
        float mx = -1e30f;
        for (int e = 0; e < E_; ++e) mx = fmaxf(mx, logits[e]);
        float p[E_]; float sum = 0.f;
        for (int e = 0; e < E_; ++e) { p[e] = expf(logits[e] - mx); sum += p[e]; }
        float inv = 1.f / sum;
        int idx[K_]; float val[K_]; float tot = 0.f;
        for (int k = 0; k < K_; ++k) {
            float best = -1.f; int bi = 0;
            for (int e = 0; e < E_; ++e) if (p[e] > best) { best = p[e]; bi = e; }
            idx[k] = bi; val[k] = best * inv; tot += val[k]; p[bi] = -2.f;
        }
        for (int k = 0; k < K_; ++k) { ti[t*K_ + k] = idx[k]; tw[t*K_ + k] = val[k] / tot; }
    }
}

// ---------------- expert routing bookkeeping ----------------
__global__ void zero_counts_kernel(int* cnt) { if (threadIdx.x < 64) cnt[threadIdx.x] = 0; }

__global__ void count_kernel(const int* __restrict__ ti, int* cnt)
{
    int i = blockIdx.x * 256 + threadIdx.x;
    if (i < NPAIR) atomicAdd(&cnt[ti[i]], 1);
}

__global__ void scan_kernel(const int* __restrict__ cnt, int* off, int* cur)
{
    if (threadIdx.x == 0) {
        int s = 0;
        for (int e = 0; e < E_; ++e) { off[e] = s; cur[e] = s; s += cnt[e]; }
        off[E_] = s;
    }
}

__global__ void scatter_kernel(const int* __restrict__ ti, const float* __restrict__ tw,
                               int* cur, int* __restrict__ tok, float* __restrict__ pw,
                               int* __restrict__ ppos)
{
    int i = blockIdx.x * 256 + threadIdx.x;
    if (i < NPAIR) {
        int e = ti[i];
        int pos = atomicAdd(&cur[e], 1);
        tok[pos] = i >> 2;
        pw[pos] = tw[i];
        ppos[i] = pos;
    }
}

// ---------------- routed experts: fused gate/up GEMM + silu*u ----------------
__global__ __launch_bounds__(256) void expert_gateup_kernel(
    const float* __restrict__ h2, const float* __restrict__ Wg_all,
    const float* __restrict__ Wu_all, const int* __restrict__ cnt,
    const int* __restrict__ off, const int* __restrict__ tok,
    float* __restrict__ act)
{
    int e = blockIdx.y;
    int n0 = blockIdx.x * 64;
    int M = cnt[e], base = off[e];
    const float* Wg = Wg_all + (size_t)e * I_ * H_;
    const float* Wu = Wu_all + (size_t)e * I_ * H_;
    __shared__ float As[16][64];
    __shared__ float Gs[16][64];
    __shared__ float Us[16][64];
    int tid = threadIdx.x;
    int tx = tid & 15, ty = tid >> 4;
    int lr = tid >> 2, lc = (tid & 3) * 4;
    int swc = lr ^ KSWZ(lc);
    const float* Gp = Wg + (size_t)(n0 + lr) * H_ + lc;
    const float* Up = Wu + (size_t)(n0 + lr) * H_ + lc;
    for (int m0 = 0; m0 < M; m0 += 64) {
        int arow = m0 + lr;
        int tk = tok[base + ((arow < M) ? arow : 0)];   // clamp; invalid rows never stored
        const float* Ap = h2 + (size_t)tk * H_ + lc;
        ull_t ag2[4][2] = {}, au2[4][2] = {};
        float4 a4 = *(const float4*)(Ap);
        float4 g4 = *(const float4*)(Gp);
        float4 u4 = *(const float4*)(Up);
        for (int k0 = 0; k0 < H_; k0 += 16) {
            __syncthreads();
            As[lc+0][swc] = a4.x; As[lc+1][swc] = a4.y; As[lc+2][swc] = a4.z; As[lc+3][swc] = a4.w;
            Gs[lc+0][swc] = g4.x; Gs[lc+1][swc] = g4.y; Gs[lc+2][swc] = g4.z; Gs[lc+3][swc] = g4.w;
            Us[lc+0][swc] = u4.x; Us[lc+1][swc] = u4.y; Us[lc+2][swc] = u4.z; Us[lc+3][swc] = u4.w;
            __syncthreads();
            if (k0 + 16 < H_) {
                a4 = *(const float4*)(Ap + k0 + 16);
                g4 = *(const float4*)(Gp + k0 + 16);
                u4 = *(const float4*)(Up + k0 + 16);
            }
#pragma unroll
            for (int kk = 0; kk < 16; ++kk) {
                int s = KSWZ(kk);
                float4 av = *(const float4*)&As[kk][(ty*4) ^ s];
                ull_t gb0 = *(const ull_t*)&Gs[kk][(tx*4) ^ s];
                ull_t gb1 = *(const ull_t*)&Gs[kk][((tx*4) ^ s) + 2];
                ull_t ub0 = *(const ull_t*)&Us[kk][(tx*4) ^ s];
                ull_t ub1 = *(const ull_t*)&Us[kk][((tx*4) ^ s) + 2];
                ull_t a0 = dup2(av.x), a1 = dup2(av.y), a2 = dup2(av.z), a3 = dup2(av.w);
                fma2(ag2[0][0], a0, gb0); fma2(ag2[0][1], a0, gb1);
                fma2(ag2[1][0], a1, gb0); fma2(ag2[1][1], a1, gb1);
                fma2(ag2[2][0], a2, gb0); fma2(ag2[2][1], a2, gb1);
                fma2(ag2[3][0], a3, gb0); fma2(ag2[3][1], a3, gb1);
                fma2(au2[0][0], a0, ub0); fma2(au2[0][1], a0, ub1);
                fma2(au2[1][0], a1, ub0); fma2(au2[1][1], a1, ub1);
                fma2(au2[2][0], a2, ub0); fma2(au2[2][1], a2, ub1);
                fma2(au2[3][0], a3, ub0); fma2(au2[3][1], a3, ub1);
            }
        }
#pragma unroll
        for (int i = 0; i < 4; ++i) {
            int row = m0 + ty*4 + i;
            if (row < M) {
#pragma unroll
                for (int j2 = 0; j2 < 2; ++j2) {
                    float2 g = unpack2(ag2[i][j2]);
                    float2 u = unpack2(au2[i][j2]);
                    float s0 = g.x / (1.f + expf(-g.x));
                    float s1 = g.y / (1.f + expf(-g.y));
                    act[(size_t)(base + row) * I_ + n0 + tx*4 + j2*2]     = s0 * u.x;
                    act[(size_t)(base + row) * I_ + n0 + tx*4 + j2*2 + 1] = s1 * u.y;
                }
            }
        }
    }
}

// ---------------- routed experts: down projection, scaled by combine weight ----
__global__ __launch_bounds__(256) void expert_down_kernel(
    const float* __restrict__ act, const float* __restrict__ Wd_all,
    const int* __restrict__ cnt, const int* __restrict__ off,
    const float* __restrict__ pw, float* __restrict__ dexp)
{
    int e = blockIdx.y;
    int n0 = blockIdx.x * 64;
    int M = cnt[e], base = off[e];
    const float* Wd = Wd_all + (size_t)e * H_ * I_;
    const float* A = act + (size_t)base * I_;
    __shared__ float As[16][64];
    __shared__ float Bs[16][64];
    int tid = threadIdx.x;
    int tx = tid & 15, ty = tid >> 4;
    int lr = tid >> 2, lc = (tid & 3) * 4;
    int swc = lr ^ KSWZ(lc);
    const float* Bp = Wd + (size_t)(n0 + lr) * I_ + lc;
    for (int m0 = 0; m0 < M; m0 += 64) {
        int arow = m0 + lr;
        const float* Ap = A + (size_t)((arow < M) ? arow : 0) * I_ + lc;
        ull_t acc2[4][2] = {};
        float4 a4 = *(const float4*)(Ap);
        float4 b4 = *(const float4*)(Bp);
        for (int k0 = 0; k0 < I_; k0 += 16) {
            __syncthreads();
            As[lc+0][swc] = a4.x; As[lc+1][swc] = a4.y; As[lc+2][swc] = a4.z; As[lc+3][swc] = a4.w;
            Bs[lc+0][swc] = b4.x; Bs[lc+1][swc] = b4.y; Bs[lc+2][swc] = b4.z; Bs[lc+3][swc] = b4.w;
            __syncthreads();
            if (k0 + 16 < I_) {
                a4 = *(const float4*)(Ap + k0 + 16);
                b4 = *(const float4*)(Bp + k0 + 16);
            }
#pragma unroll
            for (int kk = 0; kk < 16; ++kk) {
                int s = KSWZ(kk);
                float4 av = *(const float4*)&As[kk][(ty*4) ^ s];
                ull_t b0 = *(const ull_t*)&Bs[kk][(tx*4) ^ s];
                ull_t b1 = *(const ull_t*)&Bs[kk][((tx*4) ^ s) + 2];
                ull_t a0 = dup2(av.x), a1 = dup2(av.y), a2 = dup2(av.z), a3 = dup2(av.w);
                fma2(acc2[0][0], a0, b0); fma2(acc2[0][1], a0, b1);
                fma2(acc2[1][0], a1, b0); fma2(acc2[1][1], a1, b1);
                fma2(acc2[2][0], a2, b0); fma2(acc2[2][1], a2, b1);
                fma2(acc2[3][0], a3, b0); fma2(acc2[3][1], a3, b1);
            }
        }
#pragma unroll
        for (int i = 0; i < 4; ++i) {
            int row = m0 + ty*4 + i;
            if (row < M) {
                float w = pw[base + row];
#pragma unroll
                for (int j2 = 0; j2 < 2; ++j2) {
                    float2 p = unpack2(acc2[i][j2]);
                    dexp[(size_t)(base + row) * H_ + n0 + tx*4 + j2*2]     = p.x * w;
                    dexp[(size_t)(base + row) * H_ + n0 + tx*4 + j2*2 + 1] = p.y * w;
                }
            }
        }
    }
}

// ---------------- final combine: residual + gated shared + 4 routed pairs ------
__global__ void combine_kernel(const float* __restrict__ x1, const float* __restrict__ so,
                               const float* __restrict__ sgl, const float* __restrict__ dexp,
                               const int* __restrict__ ppos, float* __restrict__ out)
{
    int t = blockIdx.x;
    float g = sgl[t];
    int p0 = ppos[t*K_ + 0], p1 = ppos[t*K_ + 1], p2 = ppos[t*K_ + 2], p3 = ppos[t*K_ + 3];
    for (int h = threadIdx.x; h < H_; h += 256) {
        float v = x1[(size_t)t*H_ + h] + g * so[(size_t)t*H_ + h];
        v += dexp[(size_t)p0*H_ + h];
        v += dexp[(size_t)p1*H_ + h];
        v += dexp[(size_t)p2*H_ + h];
        v += dexp[(size_t)p3*H_ + h];
        out[(size_t)t*H_ + h] = v;
    }
}

// ---------------- launch ----------------
template <typename Tp>
static Tp* sym_addr(const void* symbol)
{
    void* p = nullptr;
    cudaGetSymbolAddress(&p, symbol);
    return (Tp*)p;
}

extern "C" void kernel_launch(void* const* d_in, const int* in_sizes, int n_in,
                              void* d_out, int out_size)
{
    const int*   positions = (const int*)  d_in[0];
    const float* x         = (const float*)d_in[1];
    const float* ln1_w     = (const float*)d_in[2];
    const float* ln2_w     = (const float*)d_in[3];
    const float* Wqkv      = (const float*)d_in[4];
    const float* bqkv      = (const float*)d_in[5];
    const float* Wo        = (const float*)d_in[6];
    const float* gate_w    = (const float*)d_in[7];
    const float* W_gate    = (const float*)d_in[8];
    const float* W_up      = (const float*)d_in[9];
    const float* W_down    = (const float*)d_in[10];
    const float* Ws_gate   = (const float*)d_in[11];
    const float* Ws_up     = (const float*)d_in[12];
    const float* Ws_down   = (const float*)d_in[13];
    const float* sg_w      = (const float*)d_in[14];
    float* out = (float*)d_out;

    float* h1   = sym_addr<float>(g_h1);
    float* qkv  = sym_addr<float>(g_qkv);
    float* sc   = sym_addr<float>(g_scores);
    float* attn = sym_addr<float>(g_attn);
    float* x1   = sym_addr<float>(g_x1);
    float* h2   = sym_addr<float>(g_h2);
    float* tw   = sym_addr<float>(g_tw);
    int*   ti   = sym_addr<int>(g_ti);
    int*   cnt  = sym_addr<int>(g_cnt);
    int*   off  = sym_addr<int>(g_off);
    int*   cur  = sym_addr<int>(g_cur);
    int*   tok  = sym_addr<int>(g_tok);
    float* pw   = sym_addr<float>(g_pw);
    int*   ppos = sym_addr<int>(g_ppos);
    float* act  = sym_addr<float>(g_act);
    float* dexp = sym_addr<float>(g_dexp);
    float* sact = sym_addr<float>(g_sact);
    float* sg   = sym_addr<float>(g_sg);
    float* so   = sym_addr<float>(g_so);
    float* sgl  = sym_addr<float>(g_sgl);

    // ---- attention ----
    rmsnorm_kernel<<<T_, 256>>>(x, ln1_w, h1);
    gemm_nt_mt128_kernel<<<dim3(QKVD/64, T_/128), 256>>>(h1, Wqkv, bqkv, nullptr, nullptr, qkv, T_, QKVD, H_);
    rope_kernel<<<dim3(T_, NH_), 64>>>(qkv, positions);
    qk_kernel<<<dim3(T_/64, T_/64, NH_), 256>>>(qkv, sc);
    softmax_kernel<<<dim3(T_, NH_), 256>>>(sc);
    pv_kernel<<<dim3(T_/64, NH_), 256>>>(sc, qkv, attn);
    gemm_nt_mt128_kernel<<<dim3(H_/64, T_/128), 256>>>(attn, Wo, nullptr, x, nullptr, x1, T_, H_, H_);

    // ---- MoE ----
    rmsnorm_kernel<<<T_, 256>>>(x1, ln2_w, h2);
    router_kernel<<<T_, 256>>>(h2, gate_w, sg_w, tw, ti, sgl);
    zero_counts_kernel<<<1, 64>>>(cnt);
    count_kernel<<<NPAIR/256, 256>>>(ti, cnt);
    scan_kernel<<<1, 32>>>(cnt, off, cur);
    scatter_kernel<<<NPAIR/256, 256>>>(ti, tw, cur, tok, pw, ppos);
    expert_gateup_kernel<<<dim3(I_/64, E_), 256>>>(h2, W_gate, W_up, cnt, off, tok, act);
    expert_down_kernel<<<dim3(H_/64, E_), 256>>>(act, W_down, cnt, off, pw, dexp);
    // shared expert: gate GEMM -> sg; up GEMM fuses silu(sg)*u -> sact; down GEMM -> so
    gemm_nt_mt128_kernel<<<dim3(SI_/64, T_/128), 256>>>(h2, Ws_gate, nullptr, nullptr, nullptr, sg, T_, SI_, H_);
    gemm_nt_mt128_kernel<<<dim3(SI_/64, T_/128), 256>>>(h2, Ws_up, nullptr, nullptr, sg, sact, T_, SI_, H_);
    gemm_nt_mt128_kernel<<<dim3(H_/64, T_/128), 256>>>(sact, Ws_down, nullptr, nullptr, nullptr, so, T_, H_, SI_);
    combine_kernel<<<T_, 256>>>(x1, so, sgl, dexp, ppos, out);
}